// round 4
// baseline (speedup 1.0000x reference)
#include <cuda_runtime.h>
#include <cstdint>

// ---------------- problem constants ----------------
#define N_NODES   100000
#define E_EDGES   1600000
#define F_DIM     128
#define H_DIM     64
#define K_CL      16
#define NEG_SLOPE 0.2f

#define SCAN_BLOCKS 98
#define SCAN_CHUNK  1024   // 98*1024 = 100352 >= N_NODES

// ---------------- device scratch (allocation-free) ----------------
__device__ float g_y1[(size_t)N_NODES * 128];   // [xl1 | xr1]  (N,128)
__device__ float g_h [(size_t)N_NODES * 64];    // elu output of layer 1
__device__ float g_y2[(size_t)N_NODES * 32];    // [xl2 | xr2]  (N,32)
__device__ float g_Wc1[128 * 128];              // [W1l | W1r] packed (K=128, N=128)
__device__ float g_Wc2[64 * 32];                // [W2l | W2r] packed (K=64, N=32)
__device__ int   g_idx64;                       // 1 if edge indices are int64

// CSR (by dst), excluding the appended self-loops (handled analytically)
__device__ int g_cnt[SCAN_BLOCKS * SCAN_CHUNK];
__device__ int g_off[N_NODES + 1];
__device__ int g_cursor[N_NODES];
__device__ int g_blocksum[SCAN_BLOCKS];
__device__ int g_blockoff[SCAN_BLOCKS];
__device__ int g_csr_src[E_EDGES];

// ---------------- packed fp32x2 helpers (Blackwell FFMA2) ----------------
__device__ __forceinline__ void ffma2(uint64_t& d, uint64_t a, uint64_t b) {
    asm("fma.rn.f32x2 %0, %1, %2, %0;" : "+l"(d) : "l"(a), "l"(b));
}
__device__ __forceinline__ uint64_t pack_dup(float x) {
    uint64_t r;
    asm("mov.b64 %0, {%1, %1};" : "=l"(r) : "f"(x));
    return r;
}
__device__ __forceinline__ void unpack2(uint64_t v, float& lo, float& hi) {
    asm("mov.b64 {%0, %1}, %2;" : "=f"(lo), "=f"(hi) : "l"(v));
}

__device__ __forceinline__ float lrelu(float x) { return x > 0.f ? x : NEG_SLOPE * x; }

// ---------------- utility kernels ----------------
__global__ void detect_idx_kernel(const void* ei) {
    const long long* p = (const long long*)ei;
    bool ok = true;
    for (int i = 0; i < 32; i++) {
        long long v = p[i];
        if (v < 0 || v >= N_NODES) ok = false;
    }
    g_idx64 = ok ? 1 : 0;
}

__global__ void pack_w_kernel(const float* __restrict__ W1l, const float* __restrict__ W1r,
                              const float* __restrict__ W2l, const float* __restrict__ W2r) {
    int t = blockIdx.x * blockDim.x + threadIdx.x;
    if (t < 128 * 128) {
        int k = t >> 7, n = t & 127;
        g_Wc1[t] = (n < 64) ? W1l[k * 64 + n] : W1r[k * 64 + (n - 64)];
    }
    if (t < 64 * 32) {
        int k = t >> 5, n = t & 31;
        g_Wc2[t] = (n < 16) ? W2l[k * 16 + n] : W2r[k * 16 + (n - 16)];
    }
}

// ---------------- CSR build ----------------
__global__ void zero_cnt_kernel() {
    int i = blockIdx.x * blockDim.x + threadIdx.x;
    if (i < SCAN_BLOCKS * SCAN_CHUNK) g_cnt[i] = 0;
}

__global__ void hist_kernel(const void* __restrict__ ei) {
    int e = blockIdx.x * blockDim.x + threadIdx.x;
    if (e >= E_EDGES) return;
    int dst;
    if (g_idx64) dst = (int)((const long long*)ei)[(size_t)E_EDGES + e];
    else         dst = ((const int*)ei)[E_EDGES + e];
    atomicAdd(&g_cnt[dst], 1);
}

__global__ void chunk_sum_kernel() {   // grid SCAN_BLOCKS, block SCAN_CHUNK
    __shared__ int sm[SCAN_CHUNK];
    int t = threadIdx.x;
    sm[t] = g_cnt[blockIdx.x * SCAN_CHUNK + t];
    __syncthreads();
    for (int d = SCAN_CHUNK / 2; d > 0; d >>= 1) {
        if (t < d) sm[t] += sm[t + d];
        __syncthreads();
    }
    if (t == 0) g_blocksum[blockIdx.x] = sm[0];
}

__global__ void scan_chunks_kernel() {  // 1 block
    if (threadIdx.x == 0) {
        int run = 0;
        for (int b = 0; b < SCAN_BLOCKS; b++) { g_blockoff[b] = run; run += g_blocksum[b]; }
        g_off[N_NODES] = run;
    }
}

__global__ void scan_final_kernel() {   // grid SCAN_BLOCKS, block SCAN_CHUNK
    __shared__ int sm[SCAN_CHUNK];
    int t = threadIdx.x;
    int i = blockIdx.x * SCAN_CHUNK + t;
    int v = g_cnt[i];
    sm[t] = v;
    __syncthreads();
    for (int d = 1; d < SCAN_CHUNK; d <<= 1) {
        int x = (t >= d) ? sm[t - d] : 0;
        __syncthreads();
        sm[t] += x;
        __syncthreads();
    }
    int excl = sm[t] - v;
    if (i < N_NODES) {
        int o = g_blockoff[blockIdx.x] + excl;
        g_off[i] = o;
        g_cursor[i] = o;
    }
}

__global__ void scatter_kernel(const void* __restrict__ ei) {
    int e = blockIdx.x * blockDim.x + threadIdx.x;
    if (e >= E_EDGES) return;
    int src, dst;
    if (g_idx64) {
        const long long* p = (const long long*)ei;
        src = (int)p[e];
        dst = (int)p[(size_t)E_EDGES + e];
    } else {
        const int* p = (const int*)ei;
        src = p[e];
        dst = p[E_EDGES + e];
    }
    int pos = atomicAdd(&g_cursor[dst], 1);
    g_csr_src[pos] = src;
}

// ---------------- GEMM 1: y1 = X @ Wc1   (M=100000, K=128, N=128), FFMA2 + vector LDS ----------------
__global__ __launch_bounds__(256) void sgemm1_kernel(const float* __restrict__ A, int M) {
    constexpr int BM = 128, BK = 8, TM = 8;
    __shared__ float As[BK][BM];
    __shared__ float Bs[BK][128];

    int tid = threadIdx.x;
    int blockRow = blockIdx.x * BM;

    int aRow = tid >> 1;            // 0..127
    int aCol = (tid & 1) * 4;       // 0 or 4
    int bRow = tid >> 5;            // 0..7
    int bCol = (tid & 31) * 4;      // 0..124

    int tRow = (tid >> 4) * TM;
    int tCol = (tid & 15) * 8;

    uint64_t acc[TM][4];
#pragma unroll
    for (int i = 0; i < TM; i++)
#pragma unroll
        for (int j = 0; j < 4; j++) acc[i][j] = 0ull;

    for (int k0 = 0; k0 < 128; k0 += BK) {
        float4 av = make_float4(0.f, 0.f, 0.f, 0.f);
        int gr = blockRow + aRow;
        if (gr < M) av = *(const float4*)(A + (size_t)gr * 128 + k0 + aCol);
        As[aCol + 0][aRow] = av.x;
        As[aCol + 1][aRow] = av.y;
        As[aCol + 2][aRow] = av.z;
        As[aCol + 3][aRow] = av.w;

        *(float4*)(&Bs[bRow][bCol]) = *(const float4*)(g_Wc1 + (size_t)(k0 + bRow) * 128 + bCol);
        __syncthreads();

#pragma unroll
        for (int k = 0; k < BK; k++) {
            float4 alo = *(const float4*)(&As[k][tRow]);
            float4 ahi = *(const float4*)(&As[k][tRow + 4]);
            uint64_t ap[TM];
            ap[0] = pack_dup(alo.x); ap[1] = pack_dup(alo.y);
            ap[2] = pack_dup(alo.z); ap[3] = pack_dup(alo.w);
            ap[4] = pack_dup(ahi.x); ap[5] = pack_dup(ahi.y);
            ap[6] = pack_dup(ahi.z); ap[7] = pack_dup(ahi.w);
            ulonglong2 b01 = *(const ulonglong2*)(&Bs[k][tCol]);
            ulonglong2 b23 = *(const ulonglong2*)(&Bs[k][tCol + 4]);
            uint64_t bp[4] = {b01.x, b01.y, b23.x, b23.y};
#pragma unroll
            for (int i = 0; i < TM; i++)
#pragma unroll
                for (int j = 0; j < 4; j++) ffma2(acc[i][j], ap[i], bp[j]);
        }
        __syncthreads();
    }

#pragma unroll
    for (int i = 0; i < TM; i++) {
        int gr = blockRow + tRow + i;
        if (gr < M) {
            float4 o0, o1;
            unpack2(acc[i][0], o0.x, o0.y);
            unpack2(acc[i][1], o0.z, o0.w);
            unpack2(acc[i][2], o1.x, o1.y);
            unpack2(acc[i][3], o1.z, o1.w);
            *(float4*)(g_y1 + (size_t)gr * 128 + tCol)     = o0;
            *(float4*)(g_y1 + (size_t)gr * 128 + tCol + 4) = o1;
        }
    }
}

// ---------------- layer-1 aggregation: warp per dst node, CSR gather ----------------
// h[i] = elu( (sum_j w_ij xl_j) / (sum_j w_ij) + b1 ),  w_ij = exp(a1 . lrelu(xl_j + xr_i))
__global__ __launch_bounds__(256) void agg1_kernel(const float* __restrict__ a1,
                                                   const float* __restrict__ b1) {
    int i = (blockIdx.x * blockDim.x + threadIdx.x) >> 5;   // node (exact: 12500*8 warps)
    int lane = threadIdx.x & 31;
    int c = 2 * lane;

    float2 xr = *(const float2*)(g_y1 + (size_t)i * 128 + 64 + c);
    float2 xs = *(const float2*)(g_y1 + (size_t)i * 128 + c);
    float2 aa = *(const float2*)(a1 + c);

    // self loop
    float p = lrelu(xs.x + xr.x) * aa.x + lrelu(xs.y + xr.y) * aa.y;
#pragma unroll
    for (int o = 16; o >= 1; o >>= 1) p += __shfl_xor_sync(0xffffffffu, p, o);
    float w = __expf(p);
    float denom = w;
    float acc0 = w * xs.x, acc1 = w * xs.y;

    int j = g_off[i], end = g_off[i + 1];
    for (; j + 2 <= end; j += 2) {
        int s0 = g_csr_src[j], s1 = g_csr_src[j + 1];
        float2 x0 = *(const float2*)(g_y1 + (size_t)s0 * 128 + c);
        float2 x1 = *(const float2*)(g_y1 + (size_t)s1 * 128 + c);
        float p0 = lrelu(x0.x + xr.x) * aa.x + lrelu(x0.y + xr.y) * aa.y;
        float p1 = lrelu(x1.x + xr.x) * aa.x + lrelu(x1.y + xr.y) * aa.y;
#pragma unroll
        for (int o = 16; o >= 1; o >>= 1) {
            p0 += __shfl_xor_sync(0xffffffffu, p0, o);
            p1 += __shfl_xor_sync(0xffffffffu, p1, o);
        }
        float w0 = __expf(p0), w1 = __expf(p1);
        denom += w0 + w1;
        acc0 = fmaf(w0, x0.x, acc0); acc1 = fmaf(w0, x0.y, acc1);
        acc0 = fmaf(w1, x1.x, acc0); acc1 = fmaf(w1, x1.y, acc1);
    }
    if (j < end) {
        int s0 = g_csr_src[j];
        float2 x0 = *(const float2*)(g_y1 + (size_t)s0 * 128 + c);
        float p0 = lrelu(x0.x + xr.x) * aa.x + lrelu(x0.y + xr.y) * aa.y;
#pragma unroll
        for (int o = 16; o >= 1; o >>= 1) p0 += __shfl_xor_sync(0xffffffffu, p0, o);
        float w0 = __expf(p0);
        denom += w0;
        acc0 = fmaf(w0, x0.x, acc0); acc1 = fmaf(w0, x0.y, acc1);
    }

    float inv = 1.f / denom;
    float2 bb = *(const float2*)(b1 + c);
    float v0 = fmaf(acc0, inv, bb.x);
    float v1 = fmaf(acc1, inv, bb.y);
    float2 h;
    h.x = v0 > 0.f ? v0 : expm1f(v0);
    h.y = v1 > 0.f ? v1 : expm1f(v1);
    *(float2*)(g_h + (size_t)i * 64 + c) = h;
}

// ---------------- GEMM 2: y2 = h @ Wc2  (M=100000, K=64, N=32): warp per row ----------------
__global__ __launch_bounds__(256) void gemm2_kernel() {
    __shared__ float Ws[64 * 32];
    for (int i = threadIdx.x; i < 64 * 32; i += blockDim.x) Ws[i] = g_Wc2[i];
    __syncthreads();

    int row = (blockIdx.x * blockDim.x + threadIdx.x) >> 5;
    int lane = threadIdx.x & 31;
    if (row >= N_NODES) return;

    const float* hr = g_h + (size_t)row * 64;
    float h0 = hr[lane];
    float h1 = hr[lane + 32];

    float acc = 0.f;
#pragma unroll
    for (int k = 0; k < 32; k++) {
        float hv = __shfl_sync(0xffffffffu, h0, k);
        acc = fmaf(hv, Ws[k * 32 + lane], acc);
    }
#pragma unroll
    for (int k = 0; k < 32; k++) {
        float hv = __shfl_sync(0xffffffffu, h1, k);
        acc = fmaf(hv, Ws[(k + 32) * 32 + lane], acc);
    }
    g_y2[(size_t)row * 32 + lane] = acc;
}

// ---------------- layer-2 aggregation + final softmax: 16 lanes per node ----------------
__global__ __launch_bounds__(256) void agg2_kernel(const float* __restrict__ a2,
                                                   const float* __restrict__ b2,
                                                   float* __restrict__ out) {
    int i = (blockIdx.x * blockDim.x + threadIdx.x) >> 4;   // node (exact: 6250*16 groups)
    int l = threadIdx.x & 15;

    float xr = g_y2[(size_t)i * 32 + 16 + l];
    float xs = g_y2[(size_t)i * 32 + l];
    float a  = a2[l];

    // self loop
    float p = lrelu(xs + xr) * a;
#pragma unroll
    for (int o = 8; o >= 1; o >>= 1) p += __shfl_xor_sync(0xffffffffu, p, o);
    float w = __expf(p);
    float denom = w;
    float acc = w * xs;

    int j = g_off[i], end = g_off[i + 1];
    for (; j + 2 <= end; j += 2) {
        int s0 = g_csr_src[j], s1 = g_csr_src[j + 1];
        float x0 = g_y2[(size_t)s0 * 32 + l];
        float x1 = g_y2[(size_t)s1 * 32 + l];
        float p0 = lrelu(x0 + xr) * a;
        float p1 = lrelu(x1 + xr) * a;
#pragma unroll
        for (int o = 8; o >= 1; o >>= 1) {
            p0 += __shfl_xor_sync(0xffffffffu, p0, o);
            p1 += __shfl_xor_sync(0xffffffffu, p1, o);
        }
        float w0 = __expf(p0), w1 = __expf(p1);
        denom += w0 + w1;
        acc = fmaf(w0, x0, acc);
        acc = fmaf(w1, x1, acc);
    }
    if (j < end) {
        int s0 = g_csr_src[j];
        float x0 = g_y2[(size_t)s0 * 32 + l];
        float p0 = lrelu(x0 + xr) * a;
#pragma unroll
        for (int o = 8; o >= 1; o >>= 1) p0 += __shfl_xor_sync(0xffffffffu, p0, o);
        float w0 = __expf(p0);
        denom += w0;
        acc = fmaf(w0, x0, acc);
    }

    float z = fmaf(acc, 1.f / denom, b2[l]);

    float m = z;
#pragma unroll
    for (int o = 8; o >= 1; o >>= 1) m = fmaxf(m, __shfl_xor_sync(0xffffffffu, m, o));
    float ex = __expf(z - m);
    float s = ex;
#pragma unroll
    for (int o = 8; o >= 1; o >>= 1) s += __shfl_xor_sync(0xffffffffu, s, o);

    out[(size_t)i * 16 + l] = ex / s;
}

// ---------------- launch ----------------
extern "C" void kernel_launch(void* const* d_in, const int* in_sizes, int n_in,
                              void* d_out, int out_size) {
    const float* X   = (const float*)d_in[0];
    const void*  ei  = d_in[1];
    // d_in[2] = batch (unused)
    const float* W1l = (const float*)d_in[3];
    const float* W1r = (const float*)d_in[4];
    const float* a1  = (const float*)d_in[5];
    const float* b1  = (const float*)d_in[6];
    const float* W2l = (const float*)d_in[7];
    const float* W2r = (const float*)d_in[8];
    const float* a2  = (const float*)d_in[9];
    const float* b2  = (const float*)d_in[10];
    float* out = (float*)d_out;

    detect_idx_kernel<<<1, 1>>>(ei);
    pack_w_kernel<<<64, 256>>>(W1l, W1r, W2l, W2r);

    // CSR build (dst-major, self-loops excluded)
    zero_cnt_kernel<<<SCAN_BLOCKS, SCAN_CHUNK>>>();
    hist_kernel<<<(E_EDGES + 255) / 256, 256>>>(ei);
    chunk_sum_kernel<<<SCAN_BLOCKS, SCAN_CHUNK>>>();
    scan_chunks_kernel<<<1, 32>>>();
    scan_final_kernel<<<SCAN_BLOCKS, SCAN_CHUNK>>>();
    scatter_kernel<<<(E_EDGES + 255) / 256, 256>>>(ei);

    sgemm1_kernel<<<(N_NODES + 127) / 128, 256>>>(X, N_NODES);

    agg1_kernel<<<N_NODES / 8, 256>>>(a1, b1);        // 12500 blocks, warp/node

    gemm2_kernel<<<(N_NODES * 32 + 255) / 256, 256>>>();

    agg2_kernel<<<N_NODES / 16, 256>>>(a2, b2, out);  // 6250 blocks, 16 lanes/node

}

// round 5
// speedup vs baseline: 1.1278x; 1.1278x over previous
#include <cuda_runtime.h>
#include <cstdint>

// ---------------- problem constants ----------------
#define N_NODES   100000
#define E_EDGES   1600000
#define F_DIM     128
#define H_DIM     64
#define K_CL      16
#define NEG_SLOPE 0.2f

#define SCAN_BLOCKS 98
#define SCAN_CHUNK  1024   // 98*1024 = 100352 >= N_NODES

// ---------------- device scratch (allocation-free) ----------------
__device__ float g_y1[(size_t)N_NODES * 128];   // [xl1 | xr1]  (N,128)
__device__ float g_h [(size_t)N_NODES * 64];    // elu output of layer 1
__device__ float g_y2[(size_t)N_NODES * 32];    // [xl2 | xr2]  (N,32)
__device__ float g_Wc1[128 * 128];              // [W1l | W1r] packed (K=128, N=128)
__device__ float g_Wc2[64 * 32];                // [W2l | W2r] packed (K=64, N=32)
__device__ int   g_idx64;                       // 1 if edge indices are int64

// CSR (by dst), excluding the appended self-loops (handled as virtual edge)
__device__ int g_cnt[SCAN_BLOCKS * SCAN_CHUNK];
__device__ int g_off[N_NODES + 1];
__device__ int g_cursor[N_NODES];
__device__ int g_blocksum[SCAN_BLOCKS];
__device__ int g_blockoff[SCAN_BLOCKS];
__device__ int g_csr_src[E_EDGES];

// ---------------- packed fp32x2 helpers (Blackwell FFMA2) ----------------
__device__ __forceinline__ void ffma2(uint64_t& d, uint64_t a, uint64_t b) {
    asm("fma.rn.f32x2 %0, %1, %2, %0;" : "+l"(d) : "l"(a), "l"(b));
}
__device__ __forceinline__ uint64_t pack_dup(float x) {
    uint64_t r;
    asm("mov.b64 %0, {%1, %1};" : "=l"(r) : "f"(x));
    return r;
}
__device__ __forceinline__ void unpack2(uint64_t v, float& lo, float& hi) {
    asm("mov.b64 {%0, %1}, %2;" : "=f"(lo), "=f"(hi) : "l"(v));
}

__device__ __forceinline__ float lrelu(float x) { return x > 0.f ? x : NEG_SLOPE * x; }

// ---------------- utility kernels ----------------
__global__ void detect_idx_kernel(const void* ei) {
    const long long* p = (const long long*)ei;
    bool ok = true;
    for (int i = 0; i < 32; i++) {
        long long v = p[i];
        if (v < 0 || v >= N_NODES) ok = false;
    }
    g_idx64 = ok ? 1 : 0;
}

__global__ void pack_w_kernel(const float* __restrict__ W1l, const float* __restrict__ W1r,
                              const float* __restrict__ W2l, const float* __restrict__ W2r) {
    int t = blockIdx.x * blockDim.x + threadIdx.x;
    if (t < 128 * 128) {
        int k = t >> 7, n = t & 127;
        g_Wc1[t] = (n < 64) ? W1l[k * 64 + n] : W1r[k * 64 + (n - 64)];
    }
    if (t < 64 * 32) {
        int k = t >> 5, n = t & 31;
        g_Wc2[t] = (n < 16) ? W2l[k * 16 + n] : W2r[k * 16 + (n - 16)];
    }
}

// ---------------- CSR build ----------------
__global__ void zero_cnt_kernel() {
    int i = blockIdx.x * blockDim.x + threadIdx.x;
    if (i < SCAN_BLOCKS * SCAN_CHUNK) g_cnt[i] = 0;
}

__global__ void hist_kernel(const void* __restrict__ ei) {
    int e = blockIdx.x * blockDim.x + threadIdx.x;
    if (e >= E_EDGES) return;
    int dst;
    if (g_idx64) dst = (int)((const long long*)ei)[(size_t)E_EDGES + e];
    else         dst = ((const int*)ei)[E_EDGES + e];
    atomicAdd(&g_cnt[dst], 1);
}

__global__ void chunk_sum_kernel() {   // grid SCAN_BLOCKS, block SCAN_CHUNK
    __shared__ int sm[SCAN_CHUNK];
    int t = threadIdx.x;
    sm[t] = g_cnt[blockIdx.x * SCAN_CHUNK + t];
    __syncthreads();
    for (int d = SCAN_CHUNK / 2; d > 0; d >>= 1) {
        if (t < d) sm[t] += sm[t + d];
        __syncthreads();
    }
    if (t == 0) g_blocksum[blockIdx.x] = sm[0];
}

__global__ void scan_chunks_kernel() {  // 1 block
    if (threadIdx.x == 0) {
        int run = 0;
        for (int b = 0; b < SCAN_BLOCKS; b++) { g_blockoff[b] = run; run += g_blocksum[b]; }
        g_off[N_NODES] = run;
    }
}

__global__ void scan_final_kernel() {   // grid SCAN_BLOCKS, block SCAN_CHUNK
    __shared__ int sm[SCAN_CHUNK];
    int t = threadIdx.x;
    int i = blockIdx.x * SCAN_CHUNK + t;
    int v = g_cnt[i];
    sm[t] = v;
    __syncthreads();
    for (int d = 1; d < SCAN_CHUNK; d <<= 1) {
        int x = (t >= d) ? sm[t - d] : 0;
        __syncthreads();
        sm[t] += x;
        __syncthreads();
    }
    int excl = sm[t] - v;
    if (i < N_NODES) {
        int o = g_blockoff[blockIdx.x] + excl;
        g_off[i] = o;
        g_cursor[i] = o;
    }
}

__global__ void scatter_kernel(const void* __restrict__ ei) {
    int e = blockIdx.x * blockDim.x + threadIdx.x;
    if (e >= E_EDGES) return;
    int src, dst;
    if (g_idx64) {
        const long long* p = (const long long*)ei;
        src = (int)p[e];
        dst = (int)p[(size_t)E_EDGES + e];
    } else {
        const int* p = (const int*)ei;
        src = p[e];
        dst = p[E_EDGES + e];
    }
    int pos = atomicAdd(&g_cursor[dst], 1);
    g_csr_src[pos] = src;
}

// ---------------- GEMM 1: y1 = X @ Wc1 (M=100000,K=128,N=128), FFMA2 + double buffer ----------------
__global__ __launch_bounds__(256) void sgemm1_kernel(const float* __restrict__ A, int M) {
    constexpr int BM = 128, BK = 8, TM = 8;
    __shared__ float As[2][BK][BM];
    __shared__ float Bs[2][BK][128];

    int tid = threadIdx.x;
    int blockRow = blockIdx.x * BM;

    int aRow = tid >> 1;            // 0..127
    int aCol = (tid & 1) * 4;       // 0 or 4
    int bRow = tid >> 5;            // 0..7
    int bCol = (tid & 31) * 4;      // 0..124

    int tRow = (tid >> 4) * TM;
    int tCol = (tid & 15) * 8;

    int gr = blockRow + aRow;
    const float* Aptr = A + (size_t)(gr < M ? gr : 0) * 128 + aCol;
    bool aValid = (gr < M);

    uint64_t acc[TM][4];
#pragma unroll
    for (int i = 0; i < TM; i++)
#pragma unroll
        for (int j = 0; j < 4; j++) acc[i][j] = 0ull;

    // prologue: tile 0 -> buffer 0
    {
        float4 av = make_float4(0.f, 0.f, 0.f, 0.f);
        if (aValid) av = *(const float4*)(Aptr);
        float4 bv = *(const float4*)(g_Wc1 + (size_t)bRow * 128 + bCol);
        As[0][aCol + 0][aRow] = av.x;
        As[0][aCol + 1][aRow] = av.y;
        As[0][aCol + 2][aRow] = av.z;
        As[0][aCol + 3][aRow] = av.w;
        *(float4*)(&Bs[0][bRow][bCol]) = bv;
    }
    __syncthreads();

    int buf = 0;
#pragma unroll
    for (int k0 = 0; k0 < 128; k0 += BK) {
        bool has_next = (k0 + BK) < 128;
        float4 av = make_float4(0.f, 0.f, 0.f, 0.f);
        float4 bv;
        if (has_next) {
            if (aValid) av = *(const float4*)(Aptr + k0 + BK);
            bv = *(const float4*)(g_Wc1 + (size_t)(k0 + BK + bRow) * 128 + bCol);
        }

#pragma unroll
        for (int k = 0; k < BK; k++) {
            float4 alo = *(const float4*)(&As[buf][k][tRow]);
            float4 ahi = *(const float4*)(&As[buf][k][tRow + 4]);
            uint64_t ap[TM];
            ap[0] = pack_dup(alo.x); ap[1] = pack_dup(alo.y);
            ap[2] = pack_dup(alo.z); ap[3] = pack_dup(alo.w);
            ap[4] = pack_dup(ahi.x); ap[5] = pack_dup(ahi.y);
            ap[6] = pack_dup(ahi.z); ap[7] = pack_dup(ahi.w);
            ulonglong2 b01 = *(const ulonglong2*)(&Bs[buf][k][tCol]);
            ulonglong2 b23 = *(const ulonglong2*)(&Bs[buf][k][tCol + 4]);
            uint64_t bp[4] = {b01.x, b01.y, b23.x, b23.y};
#pragma unroll
            for (int i = 0; i < TM; i++)
#pragma unroll
                for (int j = 0; j < 4; j++) ffma2(acc[i][j], ap[i], bp[j]);
        }

        if (has_next) {
            int nb = buf ^ 1;
            As[nb][aCol + 0][aRow] = av.x;
            As[nb][aCol + 1][aRow] = av.y;
            As[nb][aCol + 2][aRow] = av.z;
            As[nb][aCol + 3][aRow] = av.w;
            *(float4*)(&Bs[nb][bRow][bCol]) = bv;
            __syncthreads();
            buf = nb;
        }
    }

#pragma unroll
    for (int i = 0; i < TM; i++) {
        int grr = blockRow + tRow + i;
        if (grr < M) {
            float4 o0, o1;
            unpack2(acc[i][0], o0.x, o0.y);
            unpack2(acc[i][1], o0.z, o0.w);
            unpack2(acc[i][2], o1.x, o1.y);
            unpack2(acc[i][3], o1.z, o1.w);
            *(float4*)(g_y1 + (size_t)grr * 128 + tCol)     = o0;
            *(float4*)(g_y1 + (size_t)grr * 128 + tCol + 4) = o1;
        }
    }
}

// ---------------- layer-1 aggregation: warp/node, 8 lanes/edge (4 edges in flight) ----------------
// h[i] = elu( (sum_j w_ij xl_j)/(sum_j w_ij) + b1 ),  w_ij = exp(a1 . lrelu(xl_j + xr_i))
__global__ __launch_bounds__(256) void agg1_kernel(const float* __restrict__ a1,
                                                   const float* __restrict__ b1) {
    int i = (blockIdx.x * blockDim.x + threadIdx.x) >> 5;   // node (exact: 12500*8 warps)
    int lane = threadIdx.x & 31;
    int sub = lane >> 3;      // 0..3  (edge slot within chunk)
    int sl  = lane & 7;       // 0..7  (channel group: lo = sl*4, hi = 32+sl*4)

    const float* yrow_i = g_y1 + (size_t)i * 128;
    float4 xrL = *(const float4*)(yrow_i + 64 + sl * 4);
    float4 xrH = *(const float4*)(yrow_i + 96 + sl * 4);
    float4 aL  = *(const float4*)(a1 + sl * 4);
    float4 aH  = *(const float4*)(a1 + 32 + sl * 4);

    int base = g_off[i];
    int deg  = g_off[i + 1] - base;
    int m    = deg + 1;    // + virtual self-loop at index == deg

    float wsum = 0.f;
    float4 accL = make_float4(0.f, 0.f, 0.f, 0.f);
    float4 accH = make_float4(0.f, 0.f, 0.f, 0.f);

    for (int ch = 0; ch < m; ch += 4) {
        int e = ch + sub;
        bool act = (e < m);
        int src = i;
        if (act && e < deg) src = g_csr_src[base + e];

        const float* yr = g_y1 + (size_t)src * 128;
        float4 xL = *(const float4*)(yr + sl * 4);
        float4 xH = *(const float4*)(yr + 32 + sl * 4);

        float p = lrelu(xL.x + xrL.x) * aL.x;
        p = fmaf(lrelu(xL.y + xrL.y), aL.y, p);
        p = fmaf(lrelu(xL.z + xrL.z), aL.z, p);
        p = fmaf(lrelu(xL.w + xrL.w), aL.w, p);
        p = fmaf(lrelu(xH.x + xrH.x), aH.x, p);
        p = fmaf(lrelu(xH.y + xrH.y), aH.y, p);
        p = fmaf(lrelu(xH.z + xrH.z), aH.z, p);
        p = fmaf(lrelu(xH.w + xrH.w), aH.w, p);

        // reduce within 8-lane subgroup
        p += __shfl_xor_sync(0xffffffffu, p, 4);
        p += __shfl_xor_sync(0xffffffffu, p, 2);
        p += __shfl_xor_sync(0xffffffffu, p, 1);

        float w = act ? __expf(p) : 0.f;
        wsum += w;
        accL.x = fmaf(w, xL.x, accL.x); accL.y = fmaf(w, xL.y, accL.y);
        accL.z = fmaf(w, xL.z, accL.z); accL.w = fmaf(w, xL.w, accL.w);
        accH.x = fmaf(w, xH.x, accH.x); accH.y = fmaf(w, xH.y, accH.y);
        accH.z = fmaf(w, xH.z, accH.z); accH.w = fmaf(w, xH.w, accH.w);
    }

    // cross-subgroup butterfly (masks 8, 16)
#pragma unroll
    for (int o = 8; o <= 16; o <<= 1) {
        wsum  += __shfl_xor_sync(0xffffffffu, wsum,  o);
        accL.x += __shfl_xor_sync(0xffffffffu, accL.x, o);
        accL.y += __shfl_xor_sync(0xffffffffu, accL.y, o);
        accL.z += __shfl_xor_sync(0xffffffffu, accL.z, o);
        accL.w += __shfl_xor_sync(0xffffffffu, accL.w, o);
        accH.x += __shfl_xor_sync(0xffffffffu, accH.x, o);
        accH.y += __shfl_xor_sync(0xffffffffu, accH.y, o);
        accH.z += __shfl_xor_sync(0xffffffffu, accH.z, o);
        accH.w += __shfl_xor_sync(0xffffffffu, accH.w, o);
    }

    if (sub == 0) {
        float inv = 1.f / wsum;
        float4 bL = *(const float4*)(b1 + sl * 4);
        float4 bH = *(const float4*)(b1 + 32 + sl * 4);
        float4 hL, hH;
        float v;
        v = fmaf(accL.x, inv, bL.x); hL.x = v > 0.f ? v : expm1f(v);
        v = fmaf(accL.y, inv, bL.y); hL.y = v > 0.f ? v : expm1f(v);
        v = fmaf(accL.z, inv, bL.z); hL.z = v > 0.f ? v : expm1f(v);
        v = fmaf(accL.w, inv, bL.w); hL.w = v > 0.f ? v : expm1f(v);
        v = fmaf(accH.x, inv, bH.x); hH.x = v > 0.f ? v : expm1f(v);
        v = fmaf(accH.y, inv, bH.y); hH.y = v > 0.f ? v : expm1f(v);
        v = fmaf(accH.z, inv, bH.z); hH.z = v > 0.f ? v : expm1f(v);
        v = fmaf(accH.w, inv, bH.w); hH.w = v > 0.f ? v : expm1f(v);
        *(float4*)(g_h + (size_t)i * 64 + sl * 4)      = hL;
        *(float4*)(g_h + (size_t)i * 64 + 32 + sl * 4) = hH;
    }
}

// ---------------- GEMM 2: y2 = h @ Wc2  (M=100000, K=64, N=32): warp per row ----------------
__global__ __launch_bounds__(256) void gemm2_kernel() {
    __shared__ float Ws[64 * 32];
    for (int i = threadIdx.x; i < 64 * 32; i += blockDim.x) Ws[i] = g_Wc2[i];
    __syncthreads();

    int row = (blockIdx.x * blockDim.x + threadIdx.x) >> 5;
    int lane = threadIdx.x & 31;
    if (row >= N_NODES) return;

    const float* hr = g_h + (size_t)row * 64;
    float h0 = hr[lane];
    float h1 = hr[lane + 32];

    float acc = 0.f;
#pragma unroll
    for (int k = 0; k < 32; k++) {
        float hv = __shfl_sync(0xffffffffu, h0, k);
        acc = fmaf(hv, Ws[k * 32 + lane], acc);
    }
#pragma unroll
    for (int k = 0; k < 32; k++) {
        float hv = __shfl_sync(0xffffffffu, h1, k);
        acc = fmaf(hv, Ws[(k + 32) * 32 + lane], acc);
    }
    g_y2[(size_t)row * 32 + lane] = acc;
}

// ---------------- layer-2 aggregation + softmax: warp/node, 4 lanes/edge (8 in flight) ----------------
__global__ __launch_bounds__(256) void agg2_kernel(const float* __restrict__ a2,
                                                   const float* __restrict__ b2,
                                                   float* __restrict__ out) {
    int i = (blockIdx.x * blockDim.x + threadIdx.x) >> 5;   // node (exact: 12500*8 warps)
    int lane = threadIdx.x & 31;
    int sub = lane >> 2;     // 0..7 (edge slot)
    int sl  = lane & 3;      // 0..3 (channel quad: sl*4)

    const float* yrow_i = g_y2 + (size_t)i * 32;
    float4 xr = *(const float4*)(yrow_i + 16 + sl * 4);
    float4 aq = *(const float4*)(a2 + sl * 4);

    int base = g_off[i];
    int deg  = g_off[i + 1] - base;
    int m    = deg + 1;

    float wsum = 0.f;
    float4 acc = make_float4(0.f, 0.f, 0.f, 0.f);

    for (int ch = 0; ch < m; ch += 8) {
        int e = ch + sub;
        bool act = (e < m);
        int src = i;
        if (act && e < deg) src = g_csr_src[base + e];

        float4 x = *(const float4*)(g_y2 + (size_t)src * 32 + sl * 4);

        float p = lrelu(x.x + xr.x) * aq.x;
        p = fmaf(lrelu(x.y + xr.y), aq.y, p);
        p = fmaf(lrelu(x.z + xr.z), aq.z, p);
        p = fmaf(lrelu(x.w + xr.w), aq.w, p);

        // reduce within 4-lane subgroup
        p += __shfl_xor_sync(0xffffffffu, p, 2);
        p += __shfl_xor_sync(0xffffffffu, p, 1);

        float w = act ? __expf(p) : 0.f;
        wsum += w;
        acc.x = fmaf(w, x.x, acc.x); acc.y = fmaf(w, x.y, acc.y);
        acc.z = fmaf(w, x.z, acc.z); acc.w = fmaf(w, x.w, acc.w);
    }

    // cross-subgroup butterfly (masks 4, 8, 16)
#pragma unroll
    for (int o = 4; o <= 16; o <<= 1) {
        wsum  += __shfl_xor_sync(0xffffffffu, wsum,  o);
        acc.x += __shfl_xor_sync(0xffffffffu, acc.x, o);
        acc.y += __shfl_xor_sync(0xffffffffu, acc.y, o);
        acc.z += __shfl_xor_sync(0xffffffffu, acc.z, o);
        acc.w += __shfl_xor_sync(0xffffffffu, acc.w, o);
    }

    float inv = 1.f / wsum;
    float4 bb = *(const float4*)(b2 + sl * 4);
    float4 z;
    z.x = fmaf(acc.x, inv, bb.x);
    z.y = fmaf(acc.y, inv, bb.y);
    z.z = fmaf(acc.z, inv, bb.z);
    z.w = fmaf(acc.w, inv, bb.w);

    // softmax over 16 classes: quads live on lanes sl=0..3
    float mx = fmaxf(fmaxf(z.x, z.y), fmaxf(z.z, z.w));
    mx = fmaxf(mx, __shfl_xor_sync(0xffffffffu, mx, 1));
    mx = fmaxf(mx, __shfl_xor_sync(0xffffffffu, mx, 2));

    float4 ex;
    ex.x = __expf(z.x - mx); ex.y = __expf(z.y - mx);
    ex.z = __expf(z.z - mx); ex.w = __expf(z.w - mx);
    float s = ex.x + ex.y + ex.z + ex.w;
    s += __shfl_xor_sync(0xffffffffu, s, 1);
    s += __shfl_xor_sync(0xffffffffu, s, 2);

    if (sub == 0) {
        float is = 1.f / s;
        float4 o4 = make_float4(ex.x * is, ex.y * is, ex.z * is, ex.w * is);
        *(float4*)(out + (size_t)i * 16 + sl * 4) = o4;
    }
}

// ---------------- launch ----------------
extern "C" void kernel_launch(void* const* d_in, const int* in_sizes, int n_in,
                              void* d_out, int out_size) {
    const float* X   = (const float*)d_in[0];
    const void*  ei  = d_in[1];
    // d_in[2] = batch (unused)
    const float* W1l = (const float*)d_in[3];
    const float* W1r = (const float*)d_in[4];
    const float* a1  = (const float*)d_in[5];
    const float* b1  = (const float*)d_in[6];
    const float* W2l = (const float*)d_in[7];
    const float* W2r = (const float*)d_in[8];
    const float* a2  = (const float*)d_in[9];
    const float* b2  = (const float*)d_in[10];
    float* out = (float*)d_out;

    detect_idx_kernel<<<1, 1>>>(ei);
    pack_w_kernel<<<64, 256>>>(W1l, W1r, W2l, W2r);

    // CSR build (dst-major, self-loops virtual)
    zero_cnt_kernel<<<SCAN_BLOCKS, SCAN_CHUNK>>>();
    hist_kernel<<<(E_EDGES + 255) / 256, 256>>>(ei);
    chunk_sum_kernel<<<SCAN_BLOCKS, SCAN_CHUNK>>>();
    scan_chunks_kernel<<<1, 32>>>();
    scan_final_kernel<<<SCAN_BLOCKS, SCAN_CHUNK>>>();
    scatter_kernel<<<(E_EDGES + 255) / 256, 256>>>(ei);

    sgemm1_kernel<<<(N_NODES + 127) / 128, 256>>>(X, N_NODES);

    agg1_kernel<<<N_NODES / 8, 256>>>(a1, b1);        // 12500 blocks, warp/node

    gemm2_kernel<<<(N_NODES * 32 + 255) / 256, 256>>>();

    agg2_kernel<<<N_NODES / 8, 256>>>(a2, b2, out);   // 12500 blocks, warp/node
}

// round 7
// speedup vs baseline: 1.1681x; 1.0357x over previous
#include <cuda_runtime.h>
#include <cuda_fp16.h>
#include <cstdint>

// ---------------- problem constants ----------------
#define N_NODES   100000
#define E_EDGES   1600000
#define F_DIM     128
#define H_DIM     64
#define K_CL      16
#define NEG_SLOPE 0.2f

#define SCAN_BLOCKS 98
#define SCAN_CHUNK  1024   // 98*1024 = 100352 >= N_NODES

// ---------------- device scratch (allocation-free) ----------------
__device__ float  g_y1[(size_t)N_NODES * 128];   // [xl1 | xr1]  (N,128) fp32
__device__ __half g_xl16[(size_t)N_NODES * 64];  // xl1 in fp16 (gather side)
__device__ float  g_h [(size_t)N_NODES * 64];    // elu output of layer 1
__device__ float  g_y2[(size_t)N_NODES * 32];    // [xl2 | xr2]  (N,32) fp32
__device__ __half g_y2h[(size_t)N_NODES * 16];   // xl2 in fp16 (gather side)
__device__ float  g_Wc1[128 * 128];              // [W1l | W1r] packed (K=128, N=128)
__device__ float  g_Wc2[64 * 32];                // [W2l | W2r] packed (K=64, N=32)
__device__ int    g_idx64;                       // 1 if edge indices are int64

// CSR (by dst), self-loops handled as virtual edge
__device__ int g_cnt[SCAN_BLOCKS * SCAN_CHUNK];
__device__ int g_off[N_NODES + 1];
__device__ int g_cursor[N_NODES];
__device__ int g_blocksum[SCAN_BLOCKS];
__device__ int g_blockoff[SCAN_BLOCKS];
__device__ int g_csr_src[E_EDGES];

// ---------------- packed fp32x2 helpers (Blackwell FFMA2) ----------------
__device__ __forceinline__ void ffma2(uint64_t& d, uint64_t a, uint64_t b) {
    asm("fma.rn.f32x2 %0, %1, %2, %0;" : "+l"(d) : "l"(a), "l"(b));
}
__device__ __forceinline__ uint64_t pack_dup(float x) {
    uint64_t r;
    asm("mov.b64 %0, {%1, %1};" : "=l"(r) : "f"(x));
    return r;
}
__device__ __forceinline__ void unpack2(uint64_t v, float& lo, float& hi) {
    asm("mov.b64 {%0, %1}, %2;" : "=f"(lo), "=f"(hi) : "l"(v));
}

__device__ __forceinline__ float lrelu(float x) { return x > 0.f ? x : NEG_SLOPE * x; }

// ---------------- utility kernels ----------------
__global__ void detect_idx_kernel(const void* ei) {
    const long long* p = (const long long*)ei;
    bool ok = true;
    for (int i = 0; i < 32; i++) {
        long long v = p[i];
        if (v < 0 || v >= N_NODES) ok = false;
    }
    g_idx64 = ok ? 1 : 0;
}

__global__ void pack_w_kernel(const float* __restrict__ W1l, const float* __restrict__ W1r,
                              const float* __restrict__ W2l, const float* __restrict__ W2r) {
    int t = blockIdx.x * blockDim.x + threadIdx.x;
    if (t < 128 * 128) {
        int k = t >> 7, n = t & 127;
        g_Wc1[t] = (n < 64) ? W1l[k * 64 + n] : W1r[k * 64 + (n - 64)];
    }
    if (t < 64 * 32) {
        int k = t >> 5, n = t & 31;
        g_Wc2[t] = (n < 16) ? W2l[k * 16 + n] : W2r[k * 16 + (n - 16)];
    }
}

// ---------------- CSR build ----------------
__global__ void zero_cnt_kernel() {
    int i = blockIdx.x * blockDim.x + threadIdx.x;
    if (i < SCAN_BLOCKS * SCAN_CHUNK) g_cnt[i] = 0;
}

__global__ void hist_kernel(const void* __restrict__ ei) {
    int e = blockIdx.x * blockDim.x + threadIdx.x;
    if (e >= E_EDGES) return;
    int dst;
    if (g_idx64) dst = (int)((const long long*)ei)[(size_t)E_EDGES + e];
    else         dst = ((const int*)ei)[E_EDGES + e];
    atomicAdd(&g_cnt[dst], 1);
}

__global__ void chunk_sum_kernel() {   // grid SCAN_BLOCKS, block SCAN_CHUNK
    __shared__ int sm[SCAN_CHUNK];
    int t = threadIdx.x;
    sm[t] = g_cnt[blockIdx.x * SCAN_CHUNK + t];
    __syncthreads();
    for (int d = SCAN_CHUNK / 2; d > 0; d >>= 1) {
        if (t < d) sm[t] += sm[t + d];
        __syncthreads();
    }
    if (t == 0) g_blocksum[blockIdx.x] = sm[0];
}

__global__ void scan_chunks_kernel() {  // 1 block
    if (threadIdx.x == 0) {
        int run = 0;
        for (int b = 0; b < SCAN_BLOCKS; b++) { g_blockoff[b] = run; run += g_blocksum[b]; }
        g_off[N_NODES] = run;
    }
}

__global__ void scan_final_kernel() {   // grid SCAN_BLOCKS, block SCAN_CHUNK
    __shared__ int sm[SCAN_CHUNK];
    int t = threadIdx.x;
    int i = blockIdx.x * SCAN_CHUNK + t;
    int v = g_cnt[i];
    sm[t] = v;
    __syncthreads();
    for (int d = 1; d < SCAN_CHUNK; d <<= 1) {
        int x = (t >= d) ? sm[t - d] : 0;
        __syncthreads();
        sm[t] += x;
        __syncthreads();
    }
    int excl = sm[t] - v;
    if (i < N_NODES) {
        int o = g_blockoff[blockIdx.x] + excl;
        g_off[i] = o;
        g_cursor[i] = o;
    }
}

__global__ void scatter_kernel(const void* __restrict__ ei) {
    int e = blockIdx.x * blockDim.x + threadIdx.x;
    if (e >= E_EDGES) return;
    int src, dst;
    if (g_idx64) {
        const long long* p = (const long long*)ei;
        src = (int)p[e];
        dst = (int)p[(size_t)E_EDGES + e];
    } else {
        const int* p = (const int*)ei;
        src = p[e];
        dst = p[E_EDGES + e];
    }
    int pos = atomicAdd(&g_cursor[dst], 1);
    g_csr_src[pos] = src;
}

// ---------------- GEMM 1: y1 = X @ Wc1 (M=100000,K=128,N=128), FFMA2 + double buffer ----------------
__global__ __launch_bounds__(256) void sgemm1_kernel(const float* __restrict__ A, int M) {
    constexpr int BM = 128, BK = 8, TM = 8;
    __shared__ float As[2][BK][BM];
    __shared__ float Bs[2][BK][128];

    int tid = threadIdx.x;
    int blockRow = blockIdx.x * BM;

    int aRow = tid >> 1;            // 0..127
    int aCol = (tid & 1) * 4;       // 0 or 4
    int bRow = tid >> 5;            // 0..7
    int bCol = (tid & 31) * 4;      // 0..124

    int tRow = (tid >> 4) * TM;
    int tCol = (tid & 15) * 8;

    int gr = blockRow + aRow;
    const float* Aptr = A + (size_t)(gr < M ? gr : 0) * 128 + aCol;
    bool aValid = (gr < M);

    uint64_t acc[TM][4];
#pragma unroll
    for (int i = 0; i < TM; i++)
#pragma unroll
        for (int j = 0; j < 4; j++) acc[i][j] = 0ull;

    {
        float4 av = make_float4(0.f, 0.f, 0.f, 0.f);
        if (aValid) av = *(const float4*)(Aptr);
        float4 bv = *(const float4*)(g_Wc1 + (size_t)bRow * 128 + bCol);
        As[0][aCol + 0][aRow] = av.x;
        As[0][aCol + 1][aRow] = av.y;
        As[0][aCol + 2][aRow] = av.z;
        As[0][aCol + 3][aRow] = av.w;
        *(float4*)(&Bs[0][bRow][bCol]) = bv;
    }
    __syncthreads();

    int buf = 0;
#pragma unroll
    for (int k0 = 0; k0 < 128; k0 += BK) {
        bool has_next = (k0 + BK) < 128;
        float4 av = make_float4(0.f, 0.f, 0.f, 0.f);
        float4 bv;
        if (has_next) {
            if (aValid) av = *(const float4*)(Aptr + k0 + BK);
            bv = *(const float4*)(g_Wc1 + (size_t)(k0 + BK + bRow) * 128 + bCol);
        }

#pragma unroll
        for (int k = 0; k < BK; k++) {
            float4 alo = *(const float4*)(&As[buf][k][tRow]);
            float4 ahi = *(const float4*)(&As[buf][k][tRow + 4]);
            uint64_t ap[TM];
            ap[0] = pack_dup(alo.x); ap[1] = pack_dup(alo.y);
            ap[2] = pack_dup(alo.z); ap[3] = pack_dup(alo.w);
            ap[4] = pack_dup(ahi.x); ap[5] = pack_dup(ahi.y);
            ap[6] = pack_dup(ahi.z); ap[7] = pack_dup(ahi.w);
            ulonglong2 b01 = *(const ulonglong2*)(&Bs[buf][k][tCol]);
            ulonglong2 b23 = *(const ulonglong2*)(&Bs[buf][k][tCol + 4]);
            uint64_t bp[4] = {b01.x, b01.y, b23.x, b23.y};
#pragma unroll
            for (int i = 0; i < TM; i++)
#pragma unroll
                for (int j = 0; j < 4; j++) ffma2(acc[i][j], ap[i], bp[j]);
        }

        if (has_next) {
            int nb = buf ^ 1;
            As[nb][aCol + 0][aRow] = av.x;
            As[nb][aCol + 1][aRow] = av.y;
            As[nb][aCol + 2][aRow] = av.z;
            As[nb][aCol + 3][aRow] = av.w;
            *(float4*)(&Bs[nb][bRow][bCol]) = bv;
            __syncthreads();
            buf = nb;
        }
    }

#pragma unroll
    for (int i = 0; i < TM; i++) {
        int grr = blockRow + tRow + i;
        if (grr < M) {
            float4 o0, o1;
            unpack2(acc[i][0], o0.x, o0.y);
            unpack2(acc[i][1], o0.z, o0.w);
            unpack2(acc[i][2], o1.x, o1.y);
            unpack2(acc[i][3], o1.z, o1.w);
            *(float4*)(g_y1 + (size_t)grr * 128 + tCol)     = o0;
            *(float4*)(g_y1 + (size_t)grr * 128 + tCol + 4) = o1;
            if (tCol < 64) {   // xl half-precision mirror for the gather pass
                __half2 hh[4];
                hh[0] = __floats2half2_rn(o0.x, o0.y);
                hh[1] = __floats2half2_rn(o0.z, o0.w);
                hh[2] = __floats2half2_rn(o1.x, o1.y);
                hh[3] = __floats2half2_rn(o1.z, o1.w);
                *(uint4*)(g_xl16 + (size_t)grr * 64 + tCol) = *(uint4*)hh;
            }
        }
    }
}

// ---------------- layer-1 aggregation: warp/node, 8 lanes/edge, 8 edges in flight ----------------
__global__ __launch_bounds__(256) void agg1_kernel(const float* __restrict__ a1,
                                                   const float* __restrict__ b1) {
    int i = (blockIdx.x * blockDim.x + threadIdx.x) >> 5;   // node (exact: 12500*8 warps)
    int lane = threadIdx.x & 31;
    int sub = lane >> 3;      // 0..3  (edge slot within group)
    int sl  = lane & 7;       // 0..7  (channel group: 8 ch = sl*8..sl*8+7)

    const float* yrow_i = g_y1 + (size_t)i * 128;
    float4 xrA = *(const float4*)(yrow_i + 64 + sl * 8);
    float4 xrB = *(const float4*)(yrow_i + 64 + sl * 8 + 4);
    float4 aA  = *(const float4*)(a1 + sl * 8);
    float4 aB  = *(const float4*)(a1 + sl * 8 + 4);

    int base = g_off[i];
    int deg  = g_off[i + 1] - base;
    int m    = deg + 1;    // + virtual self-loop at index == deg

    float wsum = 0.f;
    float4 accA = make_float4(0.f, 0.f, 0.f, 0.f);
    float4 accB = make_float4(0.f, 0.f, 0.f, 0.f);

    for (int ch = 0; ch < m; ch += 8) {
        int e0 = ch + sub;
        int e1 = ch + 4 + sub;
        bool act0 = (e0 < m), act1 = (e1 < m);
        int s0 = i, s1 = i;
        if (act0 && e0 < deg) s0 = g_csr_src[base + e0];
        if (act1 && e1 < deg) s1 = g_csr_src[base + e1];

        uint4 r0 = *(const uint4*)(g_xl16 + (size_t)s0 * 64 + sl * 8);
        uint4 r1 = *(const uint4*)(g_xl16 + (size_t)s1 * 64 + sl * 8);

        float2 f00 = __half22float2(*(__half2*)&r0.x);
        float2 f01 = __half22float2(*(__half2*)&r0.y);
        float2 f02 = __half22float2(*(__half2*)&r0.z);
        float2 f03 = __half22float2(*(__half2*)&r0.w);
        float2 f10 = __half22float2(*(__half2*)&r1.x);
        float2 f11 = __half22float2(*(__half2*)&r1.y);
        float2 f12 = __half22float2(*(__half2*)&r1.z);
        float2 f13 = __half22float2(*(__half2*)&r1.w);

        float p0 = lrelu(f00.x + xrA.x) * aA.x;
        p0 = fmaf(lrelu(f00.y + xrA.y), aA.y, p0);
        p0 = fmaf(lrelu(f01.x + xrA.z), aA.z, p0);
        p0 = fmaf(lrelu(f01.y + xrA.w), aA.w, p0);
        p0 = fmaf(lrelu(f02.x + xrB.x), aB.x, p0);
        p0 = fmaf(lrelu(f02.y + xrB.y), aB.y, p0);
        p0 = fmaf(lrelu(f03.x + xrB.z), aB.z, p0);
        p0 = fmaf(lrelu(f03.y + xrB.w), aB.w, p0);

        float p1 = lrelu(f10.x + xrA.x) * aA.x;
        p1 = fmaf(lrelu(f10.y + xrA.y), aA.y, p1);
        p1 = fmaf(lrelu(f11.x + xrA.z), aA.z, p1);
        p1 = fmaf(lrelu(f11.y + xrA.w), aA.w, p1);
        p1 = fmaf(lrelu(f12.x + xrB.x), aB.x, p1);
        p1 = fmaf(lrelu(f12.y + xrB.y), aB.y, p1);
        p1 = fmaf(lrelu(f13.x + xrB.z), aB.z, p1);
        p1 = fmaf(lrelu(f13.y + xrB.w), aB.w, p1);

        p0 += __shfl_xor_sync(0xffffffffu, p0, 4);
        p1 += __shfl_xor_sync(0xffffffffu, p1, 4);
        p0 += __shfl_xor_sync(0xffffffffu, p0, 2);
        p1 += __shfl_xor_sync(0xffffffffu, p1, 2);
        p0 += __shfl_xor_sync(0xffffffffu, p0, 1);
        p1 += __shfl_xor_sync(0xffffffffu, p1, 1);

        float w0 = act0 ? __expf(p0) : 0.f;
        float w1 = act1 ? __expf(p1) : 0.f;
        wsum += w0 + w1;

        accA.x = fmaf(w0, f00.x, accA.x); accA.y = fmaf(w0, f00.y, accA.y);
        accA.z = fmaf(w0, f01.x, accA.z); accA.w = fmaf(w0, f01.y, accA.w);
        accB.x = fmaf(w0, f02.x, accB.x); accB.y = fmaf(w0, f02.y, accB.y);
        accB.z = fmaf(w0, f03.x, accB.z); accB.w = fmaf(w0, f03.y, accB.w);

        accA.x = fmaf(w1, f10.x, accA.x); accA.y = fmaf(w1, f10.y, accA.y);
        accA.z = fmaf(w1, f11.x, accA.z); accA.w = fmaf(w1, f11.y, accA.w);
        accB.x = fmaf(w1, f12.x, accB.x); accB.y = fmaf(w1, f12.y, accB.y);
        accB.z = fmaf(w1, f13.x, accB.z); accB.w = fmaf(w1, f13.y, accB.w);
    }

    // cross-subgroup butterfly (masks 8, 16)
#pragma unroll
    for (int o = 8; o <= 16; o <<= 1) {
        wsum  += __shfl_xor_sync(0xffffffffu, wsum,  o);
        accA.x += __shfl_xor_sync(0xffffffffu, accA.x, o);
        accA.y += __shfl_xor_sync(0xffffffffu, accA.y, o);
        accA.z += __shfl_xor_sync(0xffffffffu, accA.z, o);
        accA.w += __shfl_xor_sync(0xffffffffu, accA.w, o);
        accB.x += __shfl_xor_sync(0xffffffffu, accB.x, o);
        accB.y += __shfl_xor_sync(0xffffffffu, accB.y, o);
        accB.z += __shfl_xor_sync(0xffffffffu, accB.z, o);
        accB.w += __shfl_xor_sync(0xffffffffu, accB.w, o);
    }

    if (sub == 0) {
        float inv = 1.f / wsum;
        float4 bA = *(const float4*)(b1 + sl * 8);
        float4 bB = *(const float4*)(b1 + sl * 8 + 4);
        float4 hA, hB;
        float v;
        v = fmaf(accA.x, inv, bA.x); hA.x = v > 0.f ? v : expm1f(v);
        v = fmaf(accA.y, inv, bA.y); hA.y = v > 0.f ? v : expm1f(v);
        v = fmaf(accA.z, inv, bA.z); hA.z = v > 0.f ? v : expm1f(v);
        v = fmaf(accA.w, inv, bA.w); hA.w = v > 0.f ? v : expm1f(v);
        v = fmaf(accB.x, inv, bB.x); hB.x = v > 0.f ? v : expm1f(v);
        v = fmaf(accB.y, inv, bB.y); hB.y = v > 0.f ? v : expm1f(v);
        v = fmaf(accB.z, inv, bB.z); hB.z = v > 0.f ? v : expm1f(v);
        v = fmaf(accB.w, inv, bB.w); hB.w = v > 0.f ? v : expm1f(v);
        *(float4*)(g_h + (size_t)i * 64 + sl * 8)     = hA;
        *(float4*)(g_h + (size_t)i * 64 + sl * 8 + 4) = hB;
    }
}

// ---------------- GEMM 2: y2 = h @ Wc2  (M=100000, K=64, N=32): warp per row ----------------
__global__ __launch_bounds__(256) void gemm2_kernel() {
    __shared__ float Ws[64 * 32];
    for (int i = threadIdx.x; i < 64 * 32; i += blockDim.x) Ws[i] = g_Wc2[i];
    __syncthreads();

    int row = (blockIdx.x * blockDim.x + threadIdx.x) >> 5;
    int lane = threadIdx.x & 31;
    if (row >= N_NODES) return;

    const float* hr = g_h + (size_t)row * 64;
    float h0 = hr[lane];
    float h1 = hr[lane + 32];

    float acc = 0.f;
#pragma unroll
    for (int k = 0; k < 32; k++) {
        float hv = __shfl_sync(0xffffffffu, h0, k);
        acc = fmaf(hv, Ws[k * 32 + lane], acc);
    }
#pragma unroll
    for (int k = 0; k < 32; k++) {
        float hv = __shfl_sync(0xffffffffu, h1, k);
        acc = fmaf(hv, Ws[(k + 32) * 32 + lane], acc);
    }
    g_y2[(size_t)row * 32 + lane] = acc;
    if (lane < 16) g_y2h[(size_t)row * 16 + lane] = __float2half(acc);  // xl2 fp16 mirror
}

// ---------------- layer-2 aggregation + softmax: warp/node, 4 lanes/edge, 16 edges in flight ----------------
__global__ __launch_bounds__(256) void agg2_kernel(const float* __restrict__ a2,
                                                   const float* __restrict__ b2,
                                                   float* __restrict__ out) {
    int i = (blockIdx.x * blockDim.x + threadIdx.x) >> 5;   // node (exact: 12500*8 warps)
    int lane = threadIdx.x & 31;
    int sub = lane >> 2;     // 0..7 (edge slot)
    int sl  = lane & 3;      // 0..3 (channel quad)

    const float* yrow_i = g_y2 + (size_t)i * 32;
    float4 xr = *(const float4*)(yrow_i + 16 + sl * 4);
    float4 aq = *(const float4*)(a2 + sl * 4);

    int base = g_off[i];
    int deg  = g_off[i + 1] - base;
    int m    = deg + 1;

    float wsum = 0.f;
    float4 acc = make_float4(0.f, 0.f, 0.f, 0.f);

    for (int ch = 0; ch < m; ch += 16) {
        int e0 = ch + sub, e1 = ch + 8 + sub;
        bool act0 = (e0 < m), act1 = (e1 < m);
        int s0 = i, s1 = i;
        if (act0 && e0 < deg) s0 = g_csr_src[base + e0];
        if (act1 && e1 < deg) s1 = g_csr_src[base + e1];

        uint2 r0 = *(const uint2*)(g_y2h + (size_t)s0 * 16 + sl * 4);
        uint2 r1 = *(const uint2*)(g_y2h + (size_t)s1 * 16 + sl * 4);

        float2 f00 = __half22float2(*(__half2*)&r0.x);
        float2 f01 = __half22float2(*(__half2*)&r0.y);
        float2 f10 = __half22float2(*(__half2*)&r1.x);
        float2 f11 = __half22float2(*(__half2*)&r1.y);

        float p0 = lrelu(f00.x + xr.x) * aq.x;
        p0 = fmaf(lrelu(f00.y + xr.y), aq.y, p0);
        p0 = fmaf(lrelu(f01.x + xr.z), aq.z, p0);
        p0 = fmaf(lrelu(f01.y + xr.w), aq.w, p0);

        float p1 = lrelu(f10.x + xr.x) * aq.x;
        p1 = fmaf(lrelu(f10.y + xr.y), aq.y, p1);
        p1 = fmaf(lrelu(f11.x + xr.z), aq.z, p1);
        p1 = fmaf(lrelu(f11.y + xr.w), aq.w, p1);

        p0 += __shfl_xor_sync(0xffffffffu, p0, 2);
        p1 += __shfl_xor_sync(0xffffffffu, p1, 2);
        p0 += __shfl_xor_sync(0xffffffffu, p0, 1);
        p1 += __shfl_xor_sync(0xffffffffu, p1, 1);

        float w0 = act0 ? __expf(p0) : 0.f;
        float w1 = act1 ? __expf(p1) : 0.f;
        wsum += w0 + w1;
        acc.x = fmaf(w0, f00.x, acc.x); acc.y = fmaf(w0, f00.y, acc.y);
        acc.z = fmaf(w0, f01.x, acc.z); acc.w = fmaf(w0, f01.y, acc.w);
        acc.x = fmaf(w1, f10.x, acc.x); acc.y = fmaf(w1, f10.y, acc.y);
        acc.z = fmaf(w1, f11.x, acc.z); acc.w = fmaf(w1, f11.y, acc.w);
    }

    // cross-subgroup butterfly (masks 4, 8, 16)
#pragma unroll
    for (int o = 4; o <= 16; o <<= 1) {
        wsum  += __shfl_xor_sync(0xffffffffu, wsum,  o);
        acc.x += __shfl_xor_sync(0xffffffffu, acc.x, o);
        acc.y += __shfl_xor_sync(0xffffffffu, acc.y, o);
        acc.z += __shfl_xor_sync(0xffffffffu, acc.z, o);
        acc.w += __shfl_xor_sync(0xffffffffu, acc.w, o);
    }

    float inv = 1.f / wsum;
    float4 bb = *(const float4*)(b2 + sl * 4);
    float4 z;
    z.x = fmaf(acc.x, inv, bb.x);
    z.y = fmaf(acc.y, inv, bb.y);
    z.z = fmaf(acc.z, inv, bb.z);
    z.w = fmaf(acc.w, inv, bb.w);

    float mx = fmaxf(fmaxf(z.x, z.y), fmaxf(z.z, z.w));
    mx = fmaxf(mx, __shfl_xor_sync(0xffffffffu, mx, 1));
    mx = fmaxf(mx, __shfl_xor_sync(0xffffffffu, mx, 2));

    float4 ex;
    ex.x = __expf(z.x - mx); ex.y = __expf(z.y - mx);
    ex.z = __expf(z.z - mx); ex.w = __expf(z.w - mx);
    float s = ex.x + ex.y + ex.z + ex.w;
    s += __shfl_xor_sync(0xffffffffu, s, 1);
    s += __shfl_xor_sync(0xffffffffu, s, 2);

    if (sub == 0) {
        float is = 1.f / s;
        float4 o4 = make_float4(ex.x * is, ex.y * is, ex.z * is, ex.w * is);
        *(float4*)(out + (size_t)i * 16 + sl * 4) = o4;
    }
}

// ---------------- launch ----------------
extern "C" void kernel_launch(void* const* d_in, const int* in_sizes, int n_in,
                              void* d_out, int out_size) {
    const float* X   = (const float*)d_in[0];
    const void*  ei  = d_in[1];
    // d_in[2] = batch (unused)
    const float* W1l = (const float*)d_in[3];
    const float* W1r = (const float*)d_in[4];
    const float* a1  = (const float*)d_in[5];
    const float* b1  = (const float*)d_in[6];
    const float* W2l = (const float*)d_in[7];
    const float* W2r = (const float*)d_in[8];
    const float* a2  = (const float*)d_in[9];
    const float* b2  = (const float*)d_in[10];
    float* out = (float*)d_out;

    detect_idx_kernel<<<1, 1>>>(ei);
    pack_w_kernel<<<64, 256>>>(W1l, W1r, W2l, W2r);

    // CSR build (dst-major, self-loops virtual)
    zero_cnt_kernel<<<SCAN_BLOCKS, SCAN_CHUNK>>>();
    hist_kernel<<<(E_EDGES + 255) / 256, 256>>>(ei);
    chunk_sum_kernel<<<SCAN_BLOCKS, SCAN_CHUNK>>>();
    scan_chunks_kernel<<<1, 32>>>();
    scan_final_kernel<<<SCAN_BLOCKS, SCAN_CHUNK>>>();
    scatter_kernel<<<(E_EDGES + 255) / 256, 256>>>(ei);

    sgemm1_kernel<<<(N_NODES + 127) / 128, 256>>>(X, N_NODES);

    agg1_kernel<<<N_NODES / 8, 256>>>(a1, b1);        // 12500 blocks, warp/node

    gemm2_kernel<<<(N_NODES * 32 + 255) / 256, 256>>>();

    agg2_kernel<<<N_NODES / 8, 256>>>(a2, b2, out);   // 12500 blocks, warp/node
}